// round 13
// baseline (speedup 1.0000x reference)
#include <cuda_runtime.h>

#define THREADS  256
#define WPB      8          // warps per block
#define IPW      4          // pipelined iterations (rows) per warp
#define RPB      (WPB*IPW)  // 32 rows per block
#define NTERMS   16
#define NBUCKETS 64
#define ROWF     512        // floats per row
#define ROWB     2048       // bytes per row

// Buckets padded to one 128-B L2 line each: [b][0]=sum, [b][1]=cnt.
// Zero at module load; finalizing block restores zeros each launch.
__device__ double   g_acc[NBUCKETS][16];
__device__ unsigned g_ticket;

// C = 255*ln2 + lgamma(256) - 256*ln(2*pi)
#define LOSS_C 867.968103160394f

__device__ __forceinline__ float dot4(float4 a, float4 b) {
    return a.x*b.x + a.y*b.y + a.z*b.z + a.w*b.w;
}
__device__ __forceinline__ unsigned su32(const void* p) {
    return (unsigned)__cvta_generic_to_shared(p);
}
__device__ __forceinline__ void cp16(unsigned dst, const void* src) {
    asm volatile("cp.async.cg.shared.global [%0], [%1], 16;"
                 :: "r"(dst), "l"(src) : "memory");
}
__device__ __forceinline__ void red_add_release_f64(double* p, double v) {
    asm volatile("red.add.release.gpu.global.f64 [%0], %1;"
                 :: "l"(p), "d"(v) : "memory");
}
__device__ __forceinline__ unsigned atom_add_acqrel_u32(unsigned* p, unsigned v) {
    unsigned r;
    asm volatile("atom.add.acq_rel.gpu.global.u32 %0, [%1], %2;"
                 : "=r"(r) : "l"(p), "r"(v) : "memory");
    return r;
}
__device__ __forceinline__ double ld_cg_f64(const double* p) {
    double r;
    asm volatile("ld.global.cg.f64 %0, [%1];" : "=d"(r) : "l"(p) : "memory");
    return r;
}
__device__ __forceinline__ void st_cg_f64(double* p, double v) {
    asm volatile("st.global.cg.f64 [%0], %1;" :: "l"(p), "d"(v) : "memory");
}

__global__ void __launch_bounds__(THREADS)
nll_main(const float* __restrict__ preds,
         const void*  __restrict__ target,
         const float* __restrict__ emb,
         float* __restrict__ out, int out_size, int n, long long vocab)
{
    __shared__ alignas(16) float s_e[2][WPB][ROWF];   // 32 KB double-buffered emb
    __shared__ float    sh_loss[WPB], sh_cnt[WPB];
    __shared__ unsigned s_tkt;

    int tid  = threadIdx.x;
    int lane = tid & 31;
    int w    = tid >> 5;
    int base = blockIdx.x * RPB;

    // ---- inline dtype detection (L2-broadcast of first 32 int64 words).
    // int64 buffer: all in [0,vocab) -> 0. int32 buffer: word valid only if
    // the odd slot is 0 (p~2e-5); all-32-valid is impossible.
    int di = lane < (n >> 1) ? lane : 0;
    long long dv = ((const long long*)target)[di];
    unsigned badm = __ballot_sync(0xffffffffu, dv < 0 || dv >= vocab);
    int flag32 = (badm != 0);

    // ---- ALL IPW targets in ONE parallel hop (lanes 0..IPW-1) ----
    long long t_l = 1;
    if (lane < IPW) {
        int r = base + lane * WPB + w;
        if (r < n) {
            t_l = flag32 ? (long long)((const int*)target)[r]
                         : ((const long long*)target)[r];
        }
    }

    float wsum = 0.0f, wcnt = 0.0f;

    // ---- prologue: stage iteration 0 ----
    long long tc = __shfl_sync(0xffffffffu, t_l, 0);
    int row = base + w;
    if (row >= n) tc = 1;                 // PAD => contributes nothing
    {
        const char* ge = (const char*)(emb + (size_t)tc * ROWF);
        unsigned    se = su32(&s_e[0][w][0]);
        #pragma unroll
        for (int k = 0; k < 4; k++) {
            unsigned c = (unsigned)lane + 32u * k;
            cp16(se + c * 16u, ge + (size_t)c * 16u);
        }
        asm volatile("cp.async.commit_group;" ::: "memory");
    }
    int prow = row < n ? row : 0;
    const float4* pp = reinterpret_cast<const float4*>(preds) + (size_t)prow * (ROWF/4) + lane;
    float4 a0 = pp[0], a1 = pp[32], a2 = pp[64], a3 = pp[96];

    // ---- software pipeline: prefetch it+1 while computing it ----
    #pragma unroll
    for (int it = 0; it < IPW; it++) {
        long long tn = 1;
        float4 n0 = a0, n1 = a1, n2 = a2, n3 = a3;
        if (it + 1 < IPW) {
            tn = __shfl_sync(0xffffffffu, t_l, it + 1);
            int rn = base + (it + 1) * WPB + w;
            if (rn >= n) tn = 1;
            const char* ge = (const char*)(emb + (size_t)tn * ROWF);
            unsigned    se = su32(&s_e[(it + 1) & 1][w][0]);
            #pragma unroll
            for (int k = 0; k < 4; k++) {
                unsigned c = (unsigned)lane + 32u * k;
                cp16(se + c * 16u, ge + (size_t)c * 16u);
            }
            asm volatile("cp.async.commit_group;" ::: "memory");
            int rp = rn < n ? rn : 0;
            const float4* np = reinterpret_cast<const float4*>(preds) + (size_t)rp * (ROWF/4) + lane;
            n0 = np[0]; n1 = np[32]; n2 = np[64]; n3 = np[96];
            asm volatile("cp.async.wait_group 1;" ::: "memory");   // iter it ready
        } else {
            asm volatile("cp.async.wait_group 0;" ::: "memory");
        }

        // Each lane consumes exactly the chunks it copied: no barrier needed.
        const float4* e4 = reinterpret_cast<const float4*>(&s_e[it & 1][w][0]) + lane;
        float4 b0 = e4[0], b1 = e4[32], b2 = e4[64], b3 = e4[96];

        float ss = dot4(a0,a0) + dot4(a1,a1) + dot4(a2,a2) + dot4(a3,a3);
        float dt = dot4(a0,b0) + dot4(a1,b1) + dot4(a2,b2) + dot4(a3,b3);

        #pragma unroll
        for (int o = 16; o > 0; o >>= 1) {
            ss += __shfl_down_sync(0xffffffffu, ss, o);
            dt += __shfl_down_sync(0xffffffffu, dt, o);
        }

        if (lane == 0 && tc != 1) {   // PAD_ID == 1
            float z = sqrtf(ss);
            float x = 0.25f * ss;
            // S = sum_j x^j/(j!*(256)_j); x~128 => converged before j=16.
            float S = 1.0f, term = 1.0f;
            #pragma unroll
            for (int j = 1; j < NTERMS; j++) {
                term *= x * (1.0f / ((float)j * (255.0f + (float)j)));
                S += term;
            }
            wsum += logf(S) - z - dt - LOSS_C;
            wcnt += 1.0f;
        }
        tc = tn; a0 = n0; a1 = n1; a2 = n2; a3 = n3;
    }

    if (lane == 0) { sh_loss[w] = wsum; sh_cnt[w] = wcnt; }
    __syncthreads();

    // ---- block reduce: 2 global reds + 1 ticket per block ----
    if (tid == 0) {
        float L = 0.0f, C = 0.0f;
        #pragma unroll
        for (int i = 0; i < WPB; i++) { L += sh_loss[i]; C += sh_cnt[i]; }
        int b = blockIdx.x & (NBUCKETS - 1);
        red_add_release_f64(&g_acc[b][0], (double)L);
        red_add_release_f64(&g_acc[b][1], (double)C);
        s_tkt = atom_add_acqrel_u32(&g_ticket, 1u);
    }
    __syncthreads();

    // ---- last block finalizes + resets state ----
    if (s_tkt == gridDim.x - 1) {
        double s = 0.0, c = 0.0;
        if (tid < NBUCKETS) {
            s = ld_cg_f64(&g_acc[tid][0]);
            c = ld_cg_f64(&g_acc[tid][1]);
        }
        #pragma unroll
        for (int o = 16; o > 0; o >>= 1) {
            s += __shfl_down_sync(0xffffffffu, s, o);
            c += __shfl_down_sync(0xffffffffu, c, o);
        }
        __shared__ double sh_s[2], sh_c[2];
        if (tid < NBUCKETS && lane == 0) { sh_s[tid >> 5] = s; sh_c[tid >> 5] = c; }
        __syncthreads();
        if (tid == 0) {
            float r = (float)((sh_s[0] + sh_s[1]) / (sh_c[0] + sh_c[1]));
            for (int i = 0; i < out_size; i++) out[i] = r;
            g_ticket = 0u;
        }
        if (tid < NBUCKETS) {
            st_cg_f64(&g_acc[tid][0], 0.0);
            st_cg_f64(&g_acc[tid][1], 0.0);
        }
    }
}

extern "C" void kernel_launch(void* const* d_in, const int* in_sizes, int n_in,
                              void* d_out, int out_size) {
    const float* preds  = (const float*)d_in[0];
    const void*  target = d_in[1];
    const float* emb    = (const float*)d_in[2];
    int n = in_sizes[1];                              // B*S rows
    long long vocab = (long long)(in_sizes[2] / 512); // rows of emb table

    int blocks = (n + RPB - 1) / RPB;                 // 256 for n=8192
    nll_main<<<blocks, THREADS>>>(preds, target, emb, (float*)d_out,
                                  out_size, n, vocab);
}

// round 14
// speedup vs baseline: 1.0175x; 1.0175x over previous
#include <cuda_runtime.h>

#define THREADS  256
#define WPB      8          // warps per block; 1 row per warp
#define RPB      8
#define NTERMS   16
#define NBUCKETS 64
#define ROWF     512        // floats per row
#define ROWB     2048       // bytes per row

// Buckets padded to one 128-B L2 line each: [b][0]=sum, [b][1]=cnt.
// Zero at module load; finalizing block restores zeros each launch.
__device__ double   g_acc[NBUCKETS][16];
__device__ unsigned g_ticket;

// C = 255*ln2 + lgamma(256) - 256*ln(2*pi)
#define LOSS_C 867.968103160394f

__device__ __forceinline__ float dot4(float4 a, float4 b) {
    return a.x*b.x + a.y*b.y + a.z*b.z + a.w*b.w;
}
__device__ __forceinline__ unsigned su32(const void* p) {
    return (unsigned)__cvta_generic_to_shared(p);
}
__device__ __forceinline__ void red_add_release_f64(double* p, double v) {
    asm volatile("red.add.release.gpu.global.f64 [%0], %1;"
                 :: "l"(p), "d"(v) : "memory");
}
__device__ __forceinline__ unsigned atom_add_acqrel_u32(unsigned* p, unsigned v) {
    unsigned r;
    asm volatile("atom.add.acq_rel.gpu.global.u32 %0, [%1], %2;"
                 : "=r"(r) : "l"(p), "r"(v) : "memory");
    return r;
}
__device__ __forceinline__ double ld_cg_f64(const double* p) {
    double r;
    asm volatile("ld.global.cg.f64 %0, [%1];" : "=d"(r) : "l"(p) : "memory");
    return r;
}
__device__ __forceinline__ void st_cg_f64(double* p, double v) {
    asm volatile("st.global.cg.f64 [%0], %1;" :: "l"(p), "d"(v) : "memory");
}

__global__ void __launch_bounds__(THREADS)
nll_main(const float* __restrict__ preds,
         const void*  __restrict__ target,
         const float* __restrict__ emb,
         float* __restrict__ out, int out_size, int n, long long vocab)
{
    __shared__ alignas(128) float s_emb[RPB][ROWF];   // 16 KB
    __shared__ alignas(8) unsigned long long s_mbar[WPB];
    __shared__ float    sh_loss[WPB], sh_cnt[WPB];
    __shared__ unsigned s_tkt;

    int tid  = threadIdx.x;
    int lane = tid & 31;
    int w    = tid >> 5;
    int row  = blockIdx.x * RPB + w;
    int rowc = row < n ? row : 0;

    // Per-warp mbarriers (count=1). Init then block-sync so the async proxy
    // sees initialized barriers before any bulk copy arrives on them.
    if (tid < WPB) {
        asm volatile("mbarrier.init.shared.b64 [%0], 1;"
                     :: "r"(su32(&s_mbar[tid])) : "memory");
    }
    __syncthreads();

    // ---- inline dtype detection (L2-broadcast of first 32 int64 words).
    // int64 buffer: all in [0,vocab) -> 0. int32 buffer: word i valid only
    // if the odd slot is 0 (p~2e-5); all-32-valid is impossible.
    long long dv = ((const long long*)target)[lane];
    unsigned badm = __ballot_sync(0xffffffffu, dv < 0 || dv >= vocab);
    int flag32 = (badm != 0);

    // ---- warp-autonomous pipeline, gather via ONE bulk copy ----
    unsigned mbar = su32(&s_mbar[w]);
    if (lane == 0) {
        long long t = 1;
        if (row < n) {
            t = flag32 ? (long long)((const int*)target)[row]
                       : ((const long long*)target)[row];
        }
        if (t == 1) t = 0;   // PAD or OOB: fetch row 0 (discarded), uniform path
        sh_loss[w] = 0.0f;   // reuse as scratch? no — keep separate; see below
        asm volatile("mbarrier.arrive.expect_tx.shared.b64 _, [%0], %1;"
                     :: "r"(mbar), "r"((unsigned)ROWB) : "memory");
        asm volatile(
            "cp.async.bulk.shared::cluster.global.mbarrier::complete_tx::bytes "
            "[%0], [%1], %2, [%3];"
            :: "r"(su32(&s_emb[w][0])), "l"(emb + (size_t)t * ROWF),
               "r"((unsigned)ROWB), "r"(mbar) : "memory");
    }

    // Re-derive the row's PAD status for all lanes (cheap, register-only).
    long long t_l = 1;
    if (lane == 0 && row < n) {
        t_l = flag32 ? (long long)((const int*)target)[row]
                     : ((const long long*)target)[row];
    }

    // preds to registers: 4 independent LDG.128/lane, overlapping the bulk.
    const float4* p = reinterpret_cast<const float4*>(preds) + (size_t)rowc * (ROWF/4) + lane;
    float4 a0 = p[0], a1 = p[32], a2 = p[64], a3 = p[96];

    long long t = __shfl_sync(0xffffffffu, t_l, 0);
    if (row >= n) t = 1;                 // PAD => contributes nothing

    // Wait for the bulk copy (phase 0 each launch; acquire for visibility).
    asm volatile(
        "{\n\t"
        ".reg .pred P;\n"
        "$wl_%=:\n\t"
        "mbarrier.try_wait.parity.acquire.cta.shared::cta.b64 P, [%0], 0, 0x989680;\n\t"
        "@P bra.uni $wd_%=;\n\t"
        "bra.uni $wl_%=;\n"
        "$wd_%=:\n\t"
        "}"
        :: "r"(mbar) : "memory");

    const float4* e4 = reinterpret_cast<const float4*>(&s_emb[w][0]) + lane;
    float4 b0 = e4[0], b1 = e4[32], b2 = e4[64], b3 = e4[96];

    float ss = dot4(a0,a0) + dot4(a1,a1) + dot4(a2,a2) + dot4(a3,a3);
    float dt = dot4(a0,b0) + dot4(a1,b1) + dot4(a2,b2) + dot4(a3,b3);

    #pragma unroll
    for (int o = 16; o > 0; o >>= 1) {
        ss += __shfl_down_sync(0xffffffffu, ss, o);
        dt += __shfl_down_sync(0xffffffffu, dt, o);
    }

    float loss = 0.0f, cnt = 0.0f;
    if (lane == 0 && t != 1) {   // PAD_ID == 1
        float z = sqrtf(ss);
        float x = 0.25f * ss;
        // S = sum_j x^j / (j! * (256)_j); x ~ 128 => converged well before j=16.
        float S = 1.0f, term = 1.0f;
        #pragma unroll
        for (int j = 1; j < NTERMS; j++) {
            term *= x * (1.0f / ((float)j * (255.0f + (float)j)));
            S += term;
        }
        loss = logf(S) - z - dt - LOSS_C;
        cnt  = 1.0f;
    }
    if (lane == 0) { sh_loss[w] = loss; sh_cnt[w] = cnt; }
    __syncthreads();

    // ---- block reduce: 2 global reds + 1 ticket per block ----
    if (tid == 0) {
        float L = 0.0f, C = 0.0f;
        #pragma unroll
        for (int i = 0; i < WPB; i++) { L += sh_loss[i]; C += sh_cnt[i]; }
        int b = blockIdx.x & (NBUCKETS - 1);
        red_add_release_f64(&g_acc[b][0], (double)L);
        red_add_release_f64(&g_acc[b][1], (double)C);
        s_tkt = atom_add_acqrel_u32(&g_ticket, 1u);
    }
    __syncthreads();

    // ---- last block finalizes + resets state ----
    if (s_tkt == gridDim.x - 1) {
        double s = 0.0, c = 0.0;
        if (tid < NBUCKETS) {
            s = ld_cg_f64(&g_acc[tid][0]);
            c = ld_cg_f64(&g_acc[tid][1]);
        }
        #pragma unroll
        for (int o = 16; o > 0; o >>= 1) {
            s += __shfl_down_sync(0xffffffffu, s, o);
            c += __shfl_down_sync(0xffffffffu, c, o);
        }
        __shared__ double sh_s[2], sh_c[2];
        if (tid < NBUCKETS && lane == 0) { sh_s[tid >> 5] = s; sh_c[tid >> 5] = c; }
        __syncthreads();
        if (tid == 0) {
            float r = (float)((sh_s[0] + sh_s[1]) / (sh_c[0] + sh_c[1]));
            for (int i = 0; i < out_size; i++) out[i] = r;
            g_ticket = 0u;
        }
        if (tid < NBUCKETS) {
            st_cg_f64(&g_acc[tid][0], 0.0);
            st_cg_f64(&g_acc[tid][1], 0.0);
        }
    }
}

extern "C" void kernel_launch(void* const* d_in, const int* in_sizes, int n_in,
                              void* d_out, int out_size) {
    const float* preds  = (const float*)d_in[0];
    const void*  target = d_in[1];
    const float* emb    = (const float*)d_in[2];
    int n = in_sizes[1];                              // B*S rows
    long long vocab = (long long)(in_sizes[2] / 512); // rows of emb table

    int blocks = (n + RPB - 1) / RPB;
    nll_main<<<blocks, THREADS>>>(preds, target, emb, (float*)d_out,
                                  out_size, n, vocab);
}